// round 9
// baseline (speedup 1.0000x reference)
#include <cuda_runtime.h>

// x1:   (16, 1, 224, 224) fp32
// W:    (288, 1, 3, 3)    fp32
// bias: (1, 288, 222, 222) fp32
// out:  (16, 288, 222, 222) fp32 = relu(conv_valid(x1, W) + bias)

#define B_      16
#define COUT_   288
#define CSPLIT  2
#define CPER    (COUT_ / CSPLIT)    // 144 channels per CTA
#define HIN_    224
#define WIN_    224
#define HOUT_   222
#define WOUT_   222
#define PLANE_  (HOUT_ * WOUT_)     // 49284
#define ROWS_CTA 3                  // 3 output rows per CTA (222 = 74*3)
#define IROWS   (ROWS_CTA + 2)      // 5 input rows
#define NPAIR   111                 // float2 pixel pairs per row

__global__ __launch_bounds__(128, 10) void conv_bias_relu_kernel(
    const float* __restrict__ x,
    const float* __restrict__ Wt,
    const float* __restrict__ bias,
    float* __restrict__ out)
{
    // Weights padded to 12 floats/channel: 2x LDS.128 + 1x LDS.32 per channel.
    __shared__ __align__(16) float sW[CPER * 12];      // 6912 B
    __shared__ __align__(8)  float sIn[IROWS][WIN_];   // 4480 B

    const int hg = blockIdx.x;            // 0..73
    const int b  = blockIdx.y;            // 0..15
    const int cg = blockIdx.z;            // 0..1
    const int t  = threadIdx.x;           // 0..127
    const int h0 = hg * ROWS_CTA;
    const int c0 = cg * CPER;

    // Cooperative weight load (this CTA's 144 channels), 9->12 padded.
    const float* wsrc = Wt + c0 * 9;
    for (int i = t; i < CPER * 9; i += 128) {
        int c = i / 9, j = i - c * 9;
        sW[c * 12 + j] = wsrc[i];
    }

    // Cooperative load of the 5 input rows (224 cols each).
    const float* xb = x + b * (HIN_ * WIN_);
    for (int i = t; i < IROWS * WIN_; i += 128) {
        int r = i / WIN_, w = i - r * WIN_;
        sIn[r][w] = xb[(h0 + r) * WIN_ + w];
    }

    __syncthreads();

    if (t >= NPAIR) return;   // 111 active pair-threads

    // Taps: 5 rows x 4 consecutive cols (2t..2t+3), invariant over channels.
    float tap[IROWS][4];
    #pragma unroll
    for (int r = 0; r < IROWS; r++) {
        float2 a = *reinterpret_cast<const float2*>(&sIn[r][2 * t]);
        float2 c = *reinterpret_cast<const float2*>(&sIn[r][2 * t + 2]);
        tap[r][0] = a.x; tap[r][1] = a.y; tap[r][2] = c.x; tap[r][3] = c.y;
    }

    // 32-bit offsets (max tensor 227M elems < 2^31).
    const int ofs = c0 * PLANE_ + h0 * WOUT_ + 2 * t;        // 8B aligned
    const float* bp = bias + ofs;
    float*       op = out + b * (COUT_ * PLANE_) + ofs;

    #pragma unroll 2
    for (int c = 0; c < CPER; c++) {
        const float4 wA = *reinterpret_cast<const float4*>(&sW[c * 12]);     // w0..w3
        const float4 wB = *reinterpret_cast<const float4*>(&sW[c * 12 + 4]); // w4..w7
        const float  w8 = sW[c * 12 + 8];

        #pragma unroll
        for (int r = 0; r < ROWS_CTA; r++) {
            float y0, y1;
            y0 = tap[r][0] * wA.x;               y1 = tap[r][1] * wA.x;
            y0 = fmaf(tap[r][1], wA.y, y0);      y1 = fmaf(tap[r][2], wA.y, y1);
            y0 = fmaf(tap[r][2], wA.z, y0);      y1 = fmaf(tap[r][3], wA.z, y1);
            y0 = fmaf(tap[r+1][0], wA.w, y0);    y1 = fmaf(tap[r+1][1], wA.w, y1);
            y0 = fmaf(tap[r+1][1], wB.x, y0);    y1 = fmaf(tap[r+1][2], wB.x, y1);
            y0 = fmaf(tap[r+1][2], wB.y, y0);    y1 = fmaf(tap[r+1][3], wB.y, y1);
            y0 = fmaf(tap[r+2][0], wB.z, y0);    y1 = fmaf(tap[r+2][1], wB.z, y1);
            y0 = fmaf(tap[r+2][1], wB.w, y0);    y1 = fmaf(tap[r+2][2], wB.w, y1);
            y0 = fmaf(tap[r+2][2], w8,  y0);     y1 = fmaf(tap[r+2][3], w8,  y1);

            const float2 bv = __ldg(reinterpret_cast<const float2*>(bp + r * WOUT_));
            float2 o;
            o.x = fmaxf(y0 + bv.x, 0.0f);
            o.y = fmaxf(y1 + bv.y, 0.0f);
            *reinterpret_cast<float2*>(op + r * WOUT_) = o;
        }
        bp += PLANE_;
        op += PLANE_;
    }
}

extern "C" void kernel_launch(void* const* d_in, const int* in_sizes, int n_in,
                              void* d_out, int out_size)
{
    const float* x    = (const float*)d_in[0];
    const float* Wt   = (const float*)d_in[1];
    const float* bias = (const float*)d_in[2];
    float*       out  = (float*)d_out;

    dim3 grid(HOUT_ / ROWS_CTA, B_, CSPLIT);   // 74 x 16 x 2 = 2368 CTAs
    dim3 block(128);                           // 4 warps
    conv_bias_relu_kernel<<<grid, block>>>(x, Wt, bias, out);
}

// round 11
// speedup vs baseline: 1.0634x; 1.0634x over previous
#include <cuda_runtime.h>

// x1:   (16, 1, 224, 224) fp32
// W:    (288, 1, 3, 3)    fp32
// bias: (1, 288, 222, 222) fp32
// out:  (16, 288, 222, 222) fp32 = relu(conv_valid(x1, W) + bias)

#define B_      16
#define COUT_   288
#define CSPLIT  2
#define CPER    (COUT_ / CSPLIT)  // 144 channels per CTA
#define HIN_    224
#define WIN_    224
#define HOUT_   222
#define WOUT_   222
#define PLANE_  (HOUT_ * WOUT_)   // 49284
#define ROWS_CTA 6                // 6 output rows per CTA (222 = 37*6)
#define IROWS   (ROWS_CTA + 2)    // 8 input rows
#define NPAIR   111               // float2 pixel pairs per row (222/2)

__global__ __launch_bounds__(256, 5) void conv_bias_relu_kernel(
    const float* __restrict__ x,
    const float* __restrict__ Wt,
    const float* __restrict__ bias,
    float* __restrict__ out)
{
    // Weights padded to 12 floats/channel: 2x LDS.128 + 1x LDS.32 per channel.
    __shared__ __align__(16) float sW[CPER * 12];     // 6912 B
    __shared__ __align__(8)  float sIn[IROWS][WIN_];  // 7168 B

    const int hg = blockIdx.x;           // 0..36
    const int b  = blockIdx.y;           // 0..15
    const int cg = blockIdx.z;           // 0..1
    const int t  = threadIdx.x;          // 0..255
    const int h0 = hg * ROWS_CTA;
    const int c0 = cg * CPER;

    // Cooperative weight load (this CTA's 144 channels), 9->12 padded.
    const float* wsrc = Wt + c0 * 9;
    for (int i = t; i < CPER * 9; i += 256) {
        int c = i / 9, j = i - c * 9;
        sW[c * 12 + j] = wsrc[i];
    }

    // Cooperative load of the 8 input rows (threads 0..223 each take one column).
    const float* xb = x + b * (HIN_ * WIN_);
    if (t < WIN_) {
        #pragma unroll
        for (int r = 0; r < IROWS; r++) sIn[r][t] = xb[(h0 + r) * WIN_ + t];
    }

    __syncthreads();

    // Warp-aligned split: warps 0-3 -> rows h0..h0+2, warps 4-7 -> rows h0+3..h0+5.
    const int half = t >> 7;             // 0 or 1
    const int u    = t & 127;            // pair index; active if < 111
    if (u >= NPAIR) return;

    // Taps: 5 input rows x 4 consecutive cols (2u..2u+3), invariant over channels.
    float tap[5][4];
    #pragma unroll
    for (int r = 0; r < 5; r++) {
        float2 a = *reinterpret_cast<const float2*>(&sIn[half * 3 + r][2 * u]);
        float2 c = *reinterpret_cast<const float2*>(&sIn[half * 3 + r][2 * u + 2]);
        tap[r][0] = a.x; tap[r][1] = a.y; tap[r][2] = c.x; tap[r][3] = c.y;
    }

    // 32-bit offsets (max tensor 227M elems < 2^31).
    const int ofs = c0 * PLANE_ + (h0 + half * 3) * WOUT_ + 2 * u;   // 8B aligned
    const float* bp = bias + ofs;
    float*       op = out + b * (COUT_ * PLANE_) + ofs;

    #pragma unroll 2
    for (int c = 0; c < CPER; c++) {
        const float4 wA = *reinterpret_cast<const float4*>(&sW[c * 12]);     // w0..w3
        const float4 wB = *reinterpret_cast<const float4*>(&sW[c * 12 + 4]); // w4..w7
        const float  w8 = sW[c * 12 + 8];

        #pragma unroll
        for (int r = 0; r < 3; r++) {
            float y0, y1;
            y0 = tap[r][0] * wA.x;               y1 = tap[r][1] * wA.x;
            y0 = fmaf(tap[r][1], wA.y, y0);      y1 = fmaf(tap[r][2], wA.y, y1);
            y0 = fmaf(tap[r][2], wA.z, y0);      y1 = fmaf(tap[r][3], wA.z, y1);
            y0 = fmaf(tap[r+1][0], wA.w, y0);    y1 = fmaf(tap[r+1][1], wA.w, y1);
            y0 = fmaf(tap[r+1][1], wB.x, y0);    y1 = fmaf(tap[r+1][2], wB.x, y1);
            y0 = fmaf(tap[r+1][2], wB.y, y0);    y1 = fmaf(tap[r+1][3], wB.y, y1);
            y0 = fmaf(tap[r+2][0], wB.z, y0);    y1 = fmaf(tap[r+2][1], wB.z, y1);
            y0 = fmaf(tap[r+2][1], wB.w, y0);    y1 = fmaf(tap[r+2][2], wB.w, y1);
            y0 = fmaf(tap[r+2][2], w8,  y0);     y1 = fmaf(tap[r+2][3], w8,  y1);

            const float2 bv = __ldg(reinterpret_cast<const float2*>(bp + r * WOUT_));
            float2 o;
            o.x = fmaxf(y0 + bv.x, 0.0f);
            o.y = fmaxf(y1 + bv.y, 0.0f);
            *reinterpret_cast<float2*>(op + r * WOUT_) = o;
        }
        bp += PLANE_;
        op += PLANE_;
    }
}

extern "C" void kernel_launch(void* const* d_in, const int* in_sizes, int n_in,
                              void* d_out, int out_size)
{
    const float* x    = (const float*)d_in[0];
    const float* Wt   = (const float*)d_in[1];
    const float* bias = (const float*)d_in[2];
    float*       out  = (float*)d_out;

    dim3 grid(HOUT_ / ROWS_CTA, B_, CSPLIT);   // 37 x 16 x 2 = 1184 CTAs
    dim3 block(256);                           // 8 warps, halves warp-aligned
    conv_bias_relu_kernel<<<grid, block>>>(x, Wt, bias, out);
}